// round 7
// baseline (speedup 1.0000x reference)
#include <cuda_runtime.h>
#include <cstdint>

// NaiveNeuralGrid: sequential column scan with 3-tap downward row stencil + sin.
//   c'[i] = sin(c[i-2]*w[i-2,j] + c[i-1]*w[i-1,j] + c[i]*w[i,j] + b[i,j])
// 64 single-warp CTAs, 2 rows/lane, carries in registers. Cross-CTA pipeline
// via global self-validating 64-bit mailboxes (NaN canary; sin outputs are in
// [-1,1] so they can never alias it).
//
// R6 vs R5 (537us):
//  - halo weight streams (rows rA-1, rA-2) are REAL for all lanes (they ride
//    the existing cp.async ring; L2 hits) -> the 16-SHFL/chunk weight-shuffle
//    loop is deleted. Only 2 carry shfls/step remain.
//  - mailbox prefetch distance raised to 2 chunks so L2 store->load visibility
//    latency is hidden behind a full chunk of compute (no per-chunk spin).
//  - cp.async ring deepened to 8 stages.

#define WID    4096
#define NCTA   64
#define RPC    64           // rows per CTA (32 lanes * 2 rows)
#define CHUNK  8
#define NCHUNK (WID / CHUNK)
#define STAGES 8
#define NSTRM  6            // a0, b0, pA, pB, h1, h2
#define CANARY 0x7ff8dead7ff8deadULL

__device__ unsigned long long g_mbox[NCTA][WID + 8];

static __device__ __forceinline__ unsigned long long ldg_rlx(const unsigned long long* p) {
    unsigned long long v;
    asm volatile("ld.global.relaxed.gpu.b64 %0, [%1];" : "=l"(v) : "l"(p));
    return v;
}
static __device__ __forceinline__ void stg_rlx(unsigned long long* p, unsigned long long v) {
    asm volatile("st.global.relaxed.gpu.b64 [%0], %1;" :: "l"(p), "l"(v));
}
static __device__ __forceinline__ void cpasync16(uint32_t dst, const float* src) {
    asm volatile("cp.async.cg.shared.global [%0], [%1], 16;" :: "r"(dst), "l"(src) : "memory");
}

__global__ void ng_init_kernel(const float* __restrict__ x) {
    int idx = blockIdx.x * blockDim.x + threadIdx.x;
    const int total = NCTA * (WID + 8);
    if (idx >= total) return;
    int c = idx / (WID + 8);
    int s = idx % (WID + 8);
    unsigned long long v;
    if (c == 0) {
        v = 0ULL;                                  // zero boundary rows -1, -2
    } else if (s == 0) {
        unsigned lo = __float_as_uint(x[RPC * c - 2]);
        unsigned hi = __float_as_uint(x[RPC * c - 1]);
        v = ((unsigned long long)hi << 32) | lo;
    } else {
        v = CANARY;
    }
    g_mbox[c][s] = v;
}

__global__ void __launch_bounds__(32, 1) ng_scan_kernel(
    const float* __restrict__ x,
    const float* __restrict__ w,
    const float* __restrict__ b,
    float* __restrict__ out)
{
    // ring[stage][stream][lane][8 floats]; lane stride 32B, stream stride 1KB.
    __shared__ float ring[STAGES * NSTRM * 32 * 8];

    const int c  = blockIdx.x;
    const int k  = threadIdx.x;
    const int rA = c * RPC + 2 * k;          // even row owned by this lane

    const float* wA = w + (size_t)rA * WID;
    const float* wB = wA + WID;
    const float* bA = b + (size_t)rA * WID;
    const float* bB = bA + WID;

    const bool lane0 = (k == 0);
    // REAL halo rows for every lane (rows rA-1, rA-2). For lane k>0 these are
    // lane k-1's wB/wA rows -> L2 hits. Clamped at the global boundary where
    // the matching carries are hard zeros, so the values are never used.
    const int r1 = (rA >= 1) ? rA - 1 : 0;
    const int r2 = (rA >= 2) ? rA - 2 : 0;
    const float* hp1 = w + (size_t)r1 * WID;
    const float* hp2 = w + (size_t)r2 * WID;

    const float* src[NSTRM] = { wA, wB, bA, bB, hp1, hp2 };

    const uint32_t smem_base = (uint32_t)__cvta_generic_to_shared(ring);

    float cA = x[rA];
    float cB = x[rA + 1];

    const unsigned long long* mb_in  = g_mbox[c];
    unsigned long long*       mb_out = g_mbox[(c + 1 < NCTA) ? (c + 1) : c];
    const bool writer = (k == 31) && (c + 1 < NCTA);

    // ---- async-copy ring: issue one chunk (8 columns of all 6 streams) ----
#define ISSUE_CHUNK(Jc) do {                                                  \
        int st_ = (Jc) % STAGES;                                              \
        _Pragma("unroll")                                                     \
        for (int s_ = 0; s_ < NSTRM; ++s_) {                                  \
            uint32_t d_ = smem_base + (uint32_t)(((st_ * NSTRM + s_) * 32 + k) * 32); \
            const float* g_ = src[s_] + (Jc) * CHUNK;                         \
            cpasync16(d_, g_);                                                \
            cpasync16(d_ + 16, g_ + 4);                                       \
        }                                                                     \
        asm volatile("cp.async.commit_group;" ::: "memory");                  \
    } while (0)

    // Prologue: fill stages 0..STAGES-2 (7 groups in flight).
#pragma unroll
    for (int p = 0; p < STAGES - 1; ++p) ISSUE_CHUNK(p);

    // Mailbox pipeline, 2-chunk prefetch distance:
    //   cur  = chunk J   (validated)
    //   nxt  = chunk J+1 (issued one chunk ago, validated at end of J)
    //   pre2 = chunk J+2 (issued at top of J)
    unsigned long long cur[CHUNK], nxt[CHUNK], pre2[CHUNK];
#pragma unroll
    for (int t = 0; t < CHUNK; ++t) {
        unsigned long long v = ldg_rlx(mb_in + t);
        while (v == CANARY) v = ldg_rlx(mb_in + t);
        cur[t] = v;
    }
#pragma unroll
    for (int t = 0; t < CHUNK; ++t) nxt[t] = ldg_rlx(mb_in + CHUNK + t);

    float a0[CHUNK], b0[CHUNK], pA[CHUNK], pB[CHUNK], h1[CHUNK], h2[CHUNK];

#pragma unroll 1
    for (int J = 0; J < NCHUNK; ++J) {
        // Issue chunk J+2's mailbox loads now; validated a full chunk later.
        if (J + 2 < NCHUNK) {
#pragma unroll
            for (int t = 0; t < CHUNK; ++t)
                pre2[t] = ldg_rlx(mb_in + (J + 2) * CHUNK + t);
        }

        // Oldest in-flight weight chunk (J) complete once <=STAGES-2 pend.
        asm volatile("cp.async.wait_group %0;" :: "n"(STAGES - 2) : "memory");

        // LDS this chunk's streams into registers (off the chain).
        {
            const int st = J % STAGES;
            const float4* p4 = (const float4*)(ring + (size_t)(st * NSTRM * 32 * 8) + k * 8);
            float4 q0, q1;
#define PULL(dst, sidx) \
            q0 = p4[(sidx) * 64 + 0]; q1 = p4[(sidx) * 64 + 1]; \
            dst[0]=q0.x; dst[1]=q0.y; dst[2]=q0.z; dst[3]=q0.w; \
            dst[4]=q1.x; dst[5]=q1.y; dst[6]=q1.z; dst[7]=q1.w;
            PULL(a0, 0) PULL(b0, 1) PULL(pA, 2) PULL(pB, 3) PULL(h1, 4) PULL(h2, 5)
#undef PULL
        }

#pragma unroll
        for (int t = 0; t < CHUNK; ++t) {
            float u2 = __shfl_up_sync(0xffffffffu, cA, 1);
            float u1 = __shfl_up_sync(0xffffffffu, cB, 1);
            float cm2 = lane0 ? __uint_as_float((unsigned)(cur[t] & 0xffffffffu)) : u2;
            float cm1 = lane0 ? __uint_as_float((unsigned)(cur[t] >> 32))         : u1;
            // sA/sB depend only on local prev state -> computed during the shfl.
            float sA = fmaf(cA, a0[t], pA[t]);
            float sB = fmaf(cA, a0[t], fmaf(cB, b0[t], pB[t]));
            float zA = fmaf(cm1, h1[t], fmaf(cm2, h2[t], sA));
            float zB = fmaf(cm1, h1[t], sB);
            cA = __sinf(zA);
            cB = __sinf(zB);
            if (writer) {
                unsigned long long v =
                    ((unsigned long long)__float_as_uint(cB) << 32) |
                    (unsigned long long)__float_as_uint(cA);
                stg_rlx(mb_out + J * CHUNK + t + 1, v);
            }
        }

        // Validate chunk J+1 (its loads were issued a full chunk ago, so L2
        // visibility latency is already paid); rotate pre2 -> nxt.
        if (J + 1 < NCHUNK) {
#pragma unroll
            for (int t = 0; t < CHUNK; ++t) {
                unsigned long long v = nxt[t];
                while (v == CANARY) v = ldg_rlx(mb_in + (J + 1) * CHUNK + t);
                cur[t] = v;
            }
#pragma unroll
            for (int t = 0; t < CHUNK; ++t) nxt[t] = pre2[t];
        }

        // Refill the stage consumed last iteration.
        if (J + STAGES - 1 < NCHUNK) ISSUE_CHUNK(J + STAGES - 1);
    }

    out[rA]     = cA;
    out[rA + 1] = cB;
}

extern "C" void kernel_launch(void* const* d_in, const int* in_sizes, int n_in,
                              void* d_out, int out_size) {
    (void)in_sizes; (void)n_in; (void)out_size;
    const float* x = (const float*)d_in[0];
    const float* w = (const float*)d_in[1];
    const float* b = (const float*)d_in[2];
    float* out = (float*)d_out;

    const int total = NCTA * (WID + 8);
    ng_init_kernel<<<(total + 255) / 256, 256>>>(x);
    ng_scan_kernel<<<NCTA, 32>>>(x, w, b, out);
}

// round 10
// speedup vs baseline: 1.2623x; 1.2623x over previous
#include <cuda_runtime.h>
#include <cstdint>

// NaiveNeuralGrid: sequential column scan, 3-tap downward row stencil + sin.
//   c'[i] = sin(c[i-2]*w[i-2,j] + c[i-1]*w[i-1,j] + c[i]*w[i,j] + b[i,j])
// 64 CTAs x 64 threads. Warp 0 = compute (2 rows/lane, carries in regs).
// Warp 1 = transport: cp.async weight ring + mailbox poll/validate into SMEM.
// Cross-CTA pipeline via global mailboxes (NaN canary self-validation).
//
// R7 vs best (R5, 537us):
//  - warp-specialized transport (cp.async issue, mailbox spin off compute warp)
//  - halo weights read from neighbor lane's SMEM region (2 global streams and
//    all weight shuffles deleted); only lane0's halo rows stream from global
//  - mailbox back to 1-chunk effective distance (R6 proved 2-chunk adds skew)

#define WID    4096
#define NCTA   64
#define RPC    64            // rows per CTA (32 lanes * 2 rows)
#define CHUNK  8
#define NCHUNK (WID / CHUNK)
#define STAGES 8
#define PREF   7             // cp.async prefetch depth in chunks
#define CANARY 0x7ff8dead7ff8deadULL

// Stage layout (floats): wA[32][8] @0, wB @256, bA @512, bB @768,
// halo h2row @1024, h1row @1032, mbox (8 x u64) @1040. 1056 floats = 4224 B.
#define STG_F  1056

__device__ unsigned long long g_mbox[NCTA][WID + 8];

static __device__ __forceinline__ unsigned long long ldg_rlx(const unsigned long long* p) {
    unsigned long long v;
    asm volatile("ld.global.relaxed.gpu.b64 %0, [%1];" : "=l"(v) : "l"(p));
    return v;
}
static __device__ __forceinline__ void stg_rlx(unsigned long long* p, unsigned long long v) {
    asm volatile("st.global.relaxed.gpu.b64 [%0], %1;" :: "l"(p), "l"(v));
}
static __device__ __forceinline__ void cpasync16(uint32_t dst, const float* src) {
    asm volatile("cp.async.cg.shared.global [%0], [%1], 16;" :: "r"(dst), "l"(src) : "memory");
}
#define BAR_SYNC(id)   asm volatile("bar.sync %0, 64;"   :: "r"(id) : "memory")
#define BAR_ARRIVE(id) asm volatile("bar.arrive %0, 64;" :: "r"(id) : "memory")

__global__ void ng_init_kernel(const float* __restrict__ x) {
    int idx = blockIdx.x * blockDim.x + threadIdx.x;
    const int total = NCTA * (WID + 8);
    if (idx >= total) return;
    int c = idx / (WID + 8);
    int s = idx % (WID + 8);
    unsigned long long v;
    if (c == 0) {
        v = 0ULL;                                   // zero boundary rows -1,-2
    } else if (s == 0) {
        unsigned lo = __float_as_uint(x[RPC * c - 2]);
        unsigned hi = __float_as_uint(x[RPC * c - 1]);
        v = ((unsigned long long)hi << 32) | lo;
    } else {
        v = CANARY;
    }
    g_mbox[c][s] = v;
}

__global__ void __launch_bounds__(64, 1) ng_scan_kernel(
    const float* __restrict__ x,
    const float* __restrict__ w,
    const float* __restrict__ b,
    float* __restrict__ out)
{
    __shared__ __align__(128) float ring[STAGES * STG_F];

    const int tid = threadIdx.x;
    const int k   = tid & 31;
    const int wid = tid >> 5;
    const int c   = blockIdx.x;
    const int rA  = c * RPC + 2 * k;        // even row owned by lane k

    const float* wA = w + (size_t)rA * WID;
    const float* wB = wA + WID;
    const float* bA = b + (size_t)rA * WID;
    const float* bB = bA + WID;

    if (wid == 1) {
        // ---------------- transport warp ----------------
        const uint32_t smem_base = (uint32_t)__cvta_generic_to_shared(ring);
        // CTA-level halo rows (rows c*64-2, c*64-1); clamped for c==0 where the
        // matching carries are hard zeros (values never used).
        const int hr2 = (c > 0) ? c * RPC - 2 : 0;
        const int hr1 = (c > 0) ? c * RPC - 1 : 0;
        const float* hp2 = w + (size_t)hr2 * WID;
        const float* hp1 = w + (size_t)hr1 * WID;
        const unsigned long long* mb_in = g_mbox[c];

#define P_ISSUE(Jc) do {                                                      \
        uint32_t sb_ = smem_base + (uint32_t)(((Jc) & 7) * (STG_F * 4));      \
        const int off_ = (Jc) * CHUNK;                                        \
        cpasync16(sb_ +        k * 32,      wA + off_);                       \
        cpasync16(sb_ +        k * 32 + 16, wA + off_ + 4);                   \
        cpasync16(sb_ + 1024 + k * 32,      wB + off_);                       \
        cpasync16(sb_ + 1024 + k * 32 + 16, wB + off_ + 4);                   \
        cpasync16(sb_ + 2048 + k * 32,      bA + off_);                       \
        cpasync16(sb_ + 2048 + k * 32 + 16, bA + off_ + 4);                   \
        cpasync16(sb_ + 3072 + k * 32,      bB + off_);                       \
        cpasync16(sb_ + 3072 + k * 32 + 16, bB + off_ + 4);                   \
        if (k < 4) {                                                          \
            const float* hs_ = ((k < 2) ? hp2 : hp1) + off_ + (k & 1) * 4;    \
            cpasync16(sb_ + 4096 + k * 16, hs_);                              \
        }                                                                     \
        asm volatile("cp.async.commit_group;" ::: "memory");                  \
    } while (0)

#pragma unroll
        for (int p = 0; p < PREF; ++p) P_ISSUE(p);

#pragma unroll 1
        for (int J = 0; J < NCHUNK; ++J) {
            // Mailbox chunk J: 8 lanes poll one slot each, deposit into stage.
            if (k < 8) {
                const unsigned long long* p = mb_in + J * CHUNK + k;
                unsigned long long v = ldg_rlx(p);
                while (v == CANARY) v = ldg_rlx(p);
                unsigned long long* dst =
                    (unsigned long long*)(ring + (J & 7) * STG_F + 1040) + k;
                *dst = v;                                        // STS
            }
            // Chunk J's cp.async group complete once <= PREF-1 groups pend.
            asm volatile("cp.async.wait_group %0;" :: "n"(PREF - 1) : "memory");
            BAR_ARRIVE(J & 7);                                   // full[J%8]
            if (J + PREF < NCHUNK) {
                // Stage reuse for chunk J+PREF: consumer must be done with
                // chunk J+PREF-8 (n-th sync pairs with n-th consumer arrive).
                if (J >= 1) BAR_SYNC(8 + ((J + PREF) & 7));      // free
                P_ISSUE(J + PREF);
            } else {
                // keep group-count semantics for wait_group at the tail
                asm volatile("cp.async.commit_group;" ::: "memory");
            }
        }
        return;
    }

    // ---------------- compute warp ----------------
    const bool lane0  = (k == 0);
    const bool writer = (k == 31) && (c + 1 < NCTA);
    unsigned long long* mb_out = g_mbox[(c + 1 < NCTA) ? (c + 1) : c];

    float cA = x[rA];
    float cB = x[rA + 1];

    float a0[CHUNK], b0[CHUNK], pA[CHUNK], pB[CHUNK], h1[CHUNK], h2[CHUNK];
    unsigned long long cur[CHUNK];

#pragma unroll 1
    for (int J = 0; J < NCHUNK; ++J) {
        BAR_SYNC(J & 7);                                         // full[J%8]
        const float* stg = ring + (J & 7) * STG_F;

        {
            float4 q0, q1;
#define PULL(dst, foff) \
            q0 = ((const float4*)(stg + (foff)))[0]; \
            q1 = ((const float4*)(stg + (foff)))[1]; \
            dst[0]=q0.x; dst[1]=q0.y; dst[2]=q0.z; dst[3]=q0.w; \
            dst[4]=q1.x; dst[5]=q1.y; dst[6]=q1.z; dst[7]=q1.w;
            PULL(a0, k * 8)
            PULL(b0, 256 + k * 8)
            PULL(pA, 512 + k * 8)
            PULL(pB, 768 + k * 8)
            // halo weights: neighbor lane's wA/wB rows; lane0 -> halo area
            const int o2 = k ? (k - 1) * 8       : 1024;
            const int o1 = k ? 256 + (k - 1) * 8 : 1032;
            PULL(h2, o2)
            PULL(h1, o1)
#undef PULL
            const unsigned long long* mbx =
                (const unsigned long long*)(stg + 1040);
#pragma unroll
            for (int t = 0; t < CHUNK; ++t) cur[t] = mbx[t];     // broadcast
        }
        BAR_ARRIVE(8 + (J & 7));                                 // free[J%8]

#pragma unroll
        for (int t = 0; t < CHUNK; ++t) {
            float u2 = __shfl_up_sync(0xffffffffu, cA, 1);
            float u1 = __shfl_up_sync(0xffffffffu, cB, 1);
            float cm2 = lane0 ? __uint_as_float((unsigned)(cur[t] & 0xffffffffu)) : u2;
            float cm1 = lane0 ? __uint_as_float((unsigned)(cur[t] >> 32))         : u1;
            // sA/sB depend only on local prev state -> computed during shfl
            float sA = fmaf(cA, a0[t], pA[t]);
            float sB = fmaf(cA, a0[t], fmaf(cB, b0[t], pB[t]));
            float zA = fmaf(cm1, h1[t], fmaf(cm2, h2[t], sA));
            float zB = fmaf(cm1, h1[t], sB);
            cA = __sinf(zA);
            cB = __sinf(zB);
            if (writer) {
                unsigned long long v =
                    ((unsigned long long)__float_as_uint(cB) << 32) |
                    (unsigned long long)__float_as_uint(cA);
                stg_rlx(mb_out + J * CHUNK + t + 1, v);
            }
        }
    }

    out[rA]     = cA;
    out[rA + 1] = cB;
}

extern "C" void kernel_launch(void* const* d_in, const int* in_sizes, int n_in,
                              void* d_out, int out_size) {
    (void)in_sizes; (void)n_in; (void)out_size;
    const float* x = (const float*)d_in[0];
    const float* w = (const float*)d_in[1];
    const float* b = (const float*)d_in[2];
    float* out = (float*)d_out;

    const int total = NCTA * (WID + 8);
    ng_init_kernel<<<(total + 255) / 256, 256>>>(x);
    ng_scan_kernel<<<NCTA, 64>>>(x, w, b, out);
}

// round 11
// speedup vs baseline: 1.3647x; 1.0811x over previous
#include <cuda_runtime.h>
#include <cstdint>

// NaiveNeuralGrid: sequential column scan, 3-tap downward row stencil + sin.
//   c'[i] = sin(c[i-2]*w[i-2,j] + c[i-1]*w[i-1,j] + c[i]*w[i,j] + b[i,j])
// R10: 32 CTAs x 64 threads, 4 rows/lane. Key idea: with 4 rows/lane the
// shfl-exported rows (cC,cD) depend only on LOCAL prev-column state, so the
// 26-cyc SHFL leaves the serial recurrence cycle (chain ~30-43 cyc/step).
// Warp 1 = transport (cp.async ring + mailbox poll), warp 0 = compute.
// Cross-CTA pipeline via global mailboxes (NaN canary self-validation).

#define WID    4096
#define NCTA   32
#define RPC    128           // rows per CTA (32 lanes * 4 rows)
#define CHUNK  8
#define NCHUNK (WID / CHUNK)
#define STAGES 4
#define PREF   3
#define CANARY 0x7ff8dead7ff8deadULL

// Stage layout (floats): 8 streams (a0,b0,c0,d0,pA,pB,pC,pD) x 32 rows x 8
// @ 0,256,...,1792; halo h2row @2048, h1row @2056; mbox (8 u64) @2064.
#define STG_F   2080
#define STG_B   (STG_F * 4)

__device__ unsigned long long g_mbox[NCTA][WID + 8];

static __device__ __forceinline__ unsigned long long ldg_rlx(const unsigned long long* p) {
    unsigned long long v;
    asm volatile("ld.global.relaxed.gpu.b64 %0, [%1];" : "=l"(v) : "l"(p));
    return v;
}
static __device__ __forceinline__ void stg_rlx(unsigned long long* p, unsigned long long v) {
    asm volatile("st.global.relaxed.gpu.b64 [%0], %1;" :: "l"(p), "l"(v));
}
static __device__ __forceinline__ void cpasync16(uint32_t dst, const float* src) {
    asm volatile("cp.async.cg.shared.global [%0], [%1], 16;" :: "r"(dst), "l"(src) : "memory");
}
#define BAR_SYNC(id)   asm volatile("bar.sync %0, 64;"   :: "r"(id) : "memory")
#define BAR_ARRIVE(id) asm volatile("bar.arrive %0, 64;" :: "r"(id) : "memory")

__global__ void ng_init_kernel(const float* __restrict__ x) {
    int idx = blockIdx.x * blockDim.x + threadIdx.x;
    const int total = NCTA * (WID + 8);
    if (idx >= total) return;
    int c = idx / (WID + 8);
    int s = idx % (WID + 8);
    unsigned long long v;
    if (c == 0) {
        v = 0ULL;                                   // zero boundary rows -1,-2
    } else if (s == 0) {
        unsigned lo = __float_as_uint(x[RPC * c - 2]);   // row -2 (low word)
        unsigned hi = __float_as_uint(x[RPC * c - 1]);   // row -1 (high word)
        v = ((unsigned long long)hi << 32) | lo;
    } else {
        v = CANARY;
    }
    g_mbox[c][s] = v;
}

__global__ void __launch_bounds__(64, 1) ng_scan_kernel(
    const float* __restrict__ x,
    const float* __restrict__ w,
    const float* __restrict__ b,
    float* __restrict__ out)
{
    __shared__ __align__(128) float ring[STAGES * STG_F];

    const int tid = threadIdx.x;
    const int k   = tid & 31;
    const int wid = tid >> 5;
    const int c   = blockIdx.x;

    if (wid == 1) {
        // ---------------- transport warp ----------------
        const uint32_t smem_base = (uint32_t)__cvta_generic_to_shared(ring);
        const int mrow = k >> 1;          // row-group this lane serves
        const int hh   = k & 1;           // which 16B half of the 32B segment
        // Per-lane base pointers; stream delta and instr index add fixed strides.
        const float* pw = w + (size_t)(c * RPC + 4 * mrow) * WID + hh * 4;
        const float* pb = b + (size_t)(c * RPC + 4 * mrow) * WID + hh * 4;
        // CTA halo rows (c*128-2, c*128-1); clamped for c==0 (values unused
        // there: the matching carries are hard zeros).
        const float* hp2 = w + (size_t)((c > 0) ? c * RPC - 2 : 0) * WID;
        const float* hp1 = w + (size_t)((c > 0) ? c * RPC - 1 : 0) * WID;
        const unsigned long long* mb_in = g_mbox[c];
        const uint32_t dlane = (uint32_t)(mrow * 32 + hh * 16);

#define P_ISSUE(Jc) do {                                                       \
        uint32_t sb_ = smem_base + (uint32_t)(((Jc) & 3) * STG_B);             \
        const int off_ = (Jc) * CHUNK;                                         \
        _Pragma("unroll")                                                      \
        for (int dd = 0; dd < 4; ++dd) {                                       \
            _Pragma("unroll")                                                  \
            for (int i = 0; i < 2; ++i) {                                      \
                cpasync16(sb_ + (uint32_t)(dd * 1024 + i * 512) + dlane,       \
                          pw + (size_t)(64 * i + dd) * WID + off_);            \
                cpasync16(sb_ + (uint32_t)((4 + dd) * 1024 + i * 512) + dlane, \
                          pb + (size_t)(64 * i + dd) * WID + off_);            \
            }                                                                  \
        }                                                                      \
        if (k < 4) {                                                           \
            const float* hs_ = ((k < 2) ? hp2 : hp1) + off_ + (k & 1) * 4;     \
            cpasync16(sb_ + 8192u + (uint32_t)((k >> 1) * 32 + (k & 1) * 16), hs_); \
        }                                                                      \
        asm volatile("cp.async.commit_group;" ::: "memory");                   \
    } while (0)

#pragma unroll
        for (int p = 0; p < PREF; ++p) P_ISSUE(p);

#pragma unroll 1
        for (int J = 0; J < NCHUNK; ++J) {
            // Mailbox chunk J: 8 lanes poll one slot each, deposit into stage.
            if (k < 8) {
                const unsigned long long* p = mb_in + J * CHUNK + k;
                unsigned long long v = ldg_rlx(p);
                while (v == CANARY) v = ldg_rlx(p);
                ((unsigned long long*)(ring + (J & 3) * STG_F + 2064))[k] = v;
            }
            asm volatile("cp.async.wait_group %0;" :: "n"(PREF - 1) : "memory");
            BAR_ARRIVE(J & 3);                                   // full[J%4]
            if (J + PREF < NCHUNK) {
                if (J >= 1) BAR_SYNC(4 + ((J + PREF) & 3));      // free
                P_ISSUE(J + PREF);
            } else {
                asm volatile("cp.async.commit_group;" ::: "memory");
            }
        }
        return;
    }

    // ---------------- compute warp ----------------
    const int  m      = k;
    const int  rA     = c * RPC + 4 * m;            // first of 4 owned rows
    const bool lane0  = (m == 0);
    const bool writer = (m == 31) && (c + 1 < NCTA);
    unsigned long long* mb_out = g_mbox[(c + 1 < NCTA) ? (c + 1) : c];

    float cA = x[rA], cB = x[rA + 1], cC = x[rA + 2], cD = x[rA + 3];

    float a0[CHUNK], b0[CHUNK], c0[CHUNK], d0[CHUNK];
    float pA[CHUNK], pB[CHUNK], pC[CHUNK], pD[CHUNK];
    float h1[CHUNK], h2[CHUNK];
    unsigned long long cur[CHUNK];

#pragma unroll 1
    for (int J = 0; J < NCHUNK; ++J) {
        BAR_SYNC(J & 3);                                         // full[J%4]
        const float* stg = ring + (J & 3) * STG_F;

        {
            float4 q0, q1;
#define PULL(dst, foff) \
            q0 = ((const float4*)(stg + (foff)))[0]; \
            q1 = ((const float4*)(stg + (foff)))[1]; \
            dst[0]=q0.x; dst[1]=q0.y; dst[2]=q0.z; dst[3]=q0.w; \
            dst[4]=q1.x; dst[5]=q1.y; dst[6]=q1.z; dst[7]=q1.w;
            PULL(a0,        m * 8)
            PULL(b0,  256 + m * 8)
            PULL(c0,  512 + m * 8)
            PULL(d0,  768 + m * 8)
            PULL(pA, 1024 + m * 8)
            PULL(pB, 1280 + m * 8)
            PULL(pC, 1536 + m * 8)
            PULL(pD, 1792 + m * 8)
            // halo weights (rows 4m-2, 4m-1): neighbor lane's c0/d0 rows;
            // lane0 reads the CTA-halo area.
            const int o2 = m ? 512 + (m - 1) * 8 : 2048;
            const int o1 = m ? 768 + (m - 1) * 8 : 2056;
            PULL(h2, o2)
            PULL(h1, o1)
#undef PULL
            const unsigned long long* mbx = (const unsigned long long*)(stg + 2064);
#pragma unroll
            for (int t = 0; t < CHUNK; ++t) cur[t] = mbx[t];     // broadcast
        }
        BAR_ARRIVE(4 + (J & 3));                                 // free[J%4]

#pragma unroll
        for (int t = 0; t < CHUNK; ++t) {
            // Off-cycle: cC/cD (the shfl sources) never depend on shfl-in.
            float u2 = __shfl_up_sync(0xffffffffu, cC, 1);
            float u1 = __shfl_up_sync(0xffffffffu, cD, 1);
            float cm2 = lane0 ? __uint_as_float((unsigned)(cur[t] & 0xffffffffu)) : u2;
            float cm1 = lane0 ? __uint_as_float((unsigned)(cur[t] >> 32))         : u1;
            // Local rows first (these feed the next step's shfl).
            float zC = fmaf(cC, c0[t], fmaf(cB, b0[t], fmaf(cA, a0[t], pC[t])));
            float zD = fmaf(cD, d0[t], fmaf(cC, c0[t], fmaf(cB, b0[t], pD[t])));
            float zA = fmaf(cA, a0[t], fmaf(cm1, h1[t], fmaf(cm2, h2[t], pA[t])));
            float zB = fmaf(cB, b0[t], fmaf(cA, a0[t], fmaf(cm1, h1[t], pB[t])));
            cC = __sinf(zC);
            cD = __sinf(zD);
            cA = __sinf(zA);
            cB = __sinf(zB);
            if (writer) {
                unsigned long long v =
                    ((unsigned long long)__float_as_uint(cD) << 32) |
                    (unsigned long long)__float_as_uint(cC);
                stg_rlx(mb_out + J * CHUNK + t + 1, v);
            }
        }
    }

    out[rA]     = cA;
    out[rA + 1] = cB;
    out[rA + 2] = cC;
    out[rA + 3] = cD;
}

extern "C" void kernel_launch(void* const* d_in, const int* in_sizes, int n_in,
                              void* d_out, int out_size) {
    (void)in_sizes; (void)n_in; (void)out_size;
    const float* x = (const float*)d_in[0];
    const float* w = (const float*)d_in[1];
    const float* b = (const float*)d_in[2];
    float* out = (float*)d_out;

    const int total = NCTA * (WID + 8);
    ng_init_kernel<<<(total + 255) / 256, 256>>>(x);
    ng_scan_kernel<<<NCTA, 64>>>(x, w, b, out);
}